// round 1
// baseline (speedup 1.0000x reference)
#include <cuda_runtime.h>
#include <math.h>

#define B_ROWS 4096
#define N_COLS 4096
#define D_K    512
#define NSPLIT 8
#define NPER   (N_COLS / NSPLIT)   // 512 cols per split
#define BM 64
#define BN 64
#define BK 16
#define TM 4
#define TN 4
#define PAD 2

// Scratch (allocation-free rule: __device__ globals)
__device__ float g_wsq[N_COLS];
__device__ float g_xsq[B_ROWS];
__device__ float g_pval[NSPLIT * B_ROWS];
__device__ int   g_pidx[NSPLIT * B_ROWS];

// ---------------------------------------------------------------------------
// Kernel 0: per-row sum of squares for inputs (x_sq) and weights (w_sq).
// One warp per row, float4 loads, shfl reduce.
// ---------------------------------------------------------------------------
__global__ void sumsq_kernel(const float* __restrict__ x,
                             const float* __restrict__ w) {
    int warp = (blockIdx.x * blockDim.x + threadIdx.x) >> 5;
    int lane = threadIdx.x & 31;
    if (warp >= B_ROWS + N_COLS) return;
    const float* src = (warp < B_ROWS) ? (x + (size_t)warp * D_K)
                                       : (w + (size_t)(warp - B_ROWS) * D_K);
    float s = 0.f;
    #pragma unroll
    for (int k = lane * 4; k < D_K; k += 128) {
        float4 v = *reinterpret_cast<const float4*>(src + k);
        s += v.x * v.x + v.y * v.y + v.z * v.z + v.w * v.w;
    }
    #pragma unroll
    for (int o = 16; o; o >>= 1) s += __shfl_xor_sync(0xffffffffu, s, o);
    if (lane == 0) {
        if (warp < B_ROWS) g_xsq[warp] = s;
        else               g_wsq[warp - B_ROWS] = s;
    }
}

// ---------------------------------------------------------------------------
// Kernel 1: fused GEMM + argmin.
// Block (bm, ns): rows [bm*64, bm*64+64), cols [ns*512, ns*512+512) in 8
// chunks of 64. 256 threads, each owns a 4x4 microtile. fp32 FFMA
// accumulation; the final sq_dist combine replicates the reference's
// rounding: round(round(x_sq - 2*dot) + w_sq).
// ---------------------------------------------------------------------------
__global__ __launch_bounds__(256, 2)
void som_min_kernel(const float* __restrict__ X, const float* __restrict__ Wm) {
    __shared__ float As[BK][BM + PAD];
    __shared__ float Bs[BK][BN + PAD];
    __shared__ float rv[BM][16];
    __shared__ int   ri[BM][16];

    const int tid = threadIdx.x;
    const int tc  = tid & 15;        // 0..15 (n direction)
    const int tr  = tid >> 4;        // 0..15 (m direction)
    const int mbase  = blockIdx.x * BM;
    const int nsplit = blockIdx.y;

    const int ldrow = tid >> 2;          // 0..63
    const int ldk   = (tid & 3) * 4;     // 0,4,8,12

    float xs[TM];
    #pragma unroll
    for (int i = 0; i < TM; i++) xs[i] = g_xsq[mbase + tr * TM + i];

    float bestv[TM];
    int   besti[TM];
    #pragma unroll
    for (int i = 0; i < TM; i++) { bestv[i] = INFINITY; besti[i] = 0; }

    const float* Aptr = X + (size_t)(mbase + ldrow) * D_K + ldk;

    for (int chunk = 0; chunk < NPER / BN; chunk++) {
        const int nbase = nsplit * NPER + chunk * BN;
        const float* Bptr = Wm + (size_t)(nbase + ldrow) * D_K + ldk;

        float acc[TM][TN];
        #pragma unroll
        for (int i = 0; i < TM; i++)
            #pragma unroll
            for (int j = 0; j < TN; j++) acc[i][j] = 0.f;

        for (int k0 = 0; k0 < D_K; k0 += BK) {
            float4 av = *reinterpret_cast<const float4*>(Aptr + k0);
            float4 bv = *reinterpret_cast<const float4*>(Bptr + k0);
            __syncthreads();  // previous iteration's reads done
            As[ldk + 0][ldrow] = av.x; As[ldk + 1][ldrow] = av.y;
            As[ldk + 2][ldrow] = av.z; As[ldk + 3][ldrow] = av.w;
            Bs[ldk + 0][ldrow] = bv.x; Bs[ldk + 1][ldrow] = bv.y;
            Bs[ldk + 2][ldrow] = bv.z; Bs[ldk + 3][ldrow] = bv.w;
            __syncthreads();
            #pragma unroll
            for (int k = 0; k < BK; k++) {
                float a[TM], b[TN];
                #pragma unroll
                for (int i = 0; i < TM; i++) a[i] = As[k][tr * TM + i];
                #pragma unroll
                for (int j = 0; j < TN; j++) b[j] = Bs[k][tc * TN + j];
                #pragma unroll
                for (int i = 0; i < TM; i++)
                    #pragma unroll
                    for (int j = 0; j < TN; j++)
                        acc[i][j] += a[i] * b[j];
            }
        }

        // Fold this 64-col chunk into the running per-row argmin.
        #pragma unroll
        for (int j = 0; j < TN; j++) {
            const int col = nbase + tc * TN + j;
            const float wsq = g_wsq[col];
            #pragma unroll
            for (int i = 0; i < TM; i++) {
                // Match reference rounding: (x_sq - 2.0*dot) + w_sq, no FMA.
                float t = __fsub_rn(xs[i], __fmul_rn(2.0f, acc[i][j]));
                float v = __fadd_rn(t, wsq);
                if (v < bestv[i] || (v == bestv[i] && col < besti[i])) {
                    bestv[i] = v; besti[i] = col;
                }
            }
        }
    }

    // Reduce across the 16 threads (tc) sharing each row.
    __syncthreads();
    #pragma unroll
    for (int i = 0; i < TM; i++) {
        rv[tr * TM + i][tc] = bestv[i];
        ri[tr * TM + i][tc] = besti[i];
    }
    __syncthreads();
    if (tid < BM) {
        float bv = rv[tid][0];
        int   bi = ri[tid][0];
        #pragma unroll
        for (int c = 1; c < 16; c++) {
            float v = rv[tid][c]; int ix = ri[tid][c];
            if (v < bv || (v == bv && ix < bi)) { bv = v; bi = ix; }
        }
        g_pval[nsplit * B_ROWS + mbase + tid] = bv;
        g_pidx[nsplit * B_ROWS + mbase + tid] = bi;
    }
}

// ---------------------------------------------------------------------------
// Kernel 2: reduce NSPLIT partials per row, emit outputs.
// Output layout (float32): [B*2] bmu (y,x) then [B] quantization errors.
// ---------------------------------------------------------------------------
__global__ void som_reduce_kernel(float* __restrict__ out) {
    int r = blockIdx.x * blockDim.x + threadIdx.x;
    if (r >= B_ROWS) return;
    float bv = g_pval[r];
    int   bi = g_pidx[r];
    #pragma unroll
    for (int s = 1; s < NSPLIT; s++) {
        float v = g_pval[s * B_ROWS + r];
        int  ix = g_pidx[s * B_ROWS + r];
        if (v < bv || (v == bv && ix < bi)) { bv = v; bi = ix; }
    }
    out[2 * r]     = (float)(bi >> 6);   // y = idx / W  (W = 64)
    out[2 * r + 1] = (float)(bi & 63);   // x = idx % W
    out[2 * B_ROWS + r] = sqrtf(fmaxf(bv, 0.f));
}

extern "C" void kernel_launch(void* const* d_in, const int* in_sizes, int n_in,
                              void* d_out, int out_size) {
    const float* x = (const float*)d_in[0];   // inputs      (4096, 512)
    const float* w = (const float*)d_in[1];   // weights_map (64, 64, 512)
    float* out = (float*)d_out;

    {
        int warps = B_ROWS + N_COLS;           // 8192 warps
        int threads = 256;                      // 8 warps/block
        int blocks = (warps * 32 + threads - 1) / threads;
        sumsq_kernel<<<blocks, threads>>>(x, w);
    }
    {
        dim3 grid(B_ROWS / BM, NSPLIT);         // (64, 8)
        som_min_kernel<<<grid, 256>>>(x, w);
    }
    {
        som_reduce_kernel<<<(B_ROWS + 255) / 256, 256>>>(out);
    }
}

// round 3
// speedup vs baseline: 1.9663x; 1.9663x over previous
#include <cuda_runtime.h>
#include <math.h>
#include <stdint.h>

#define B_ROWS 4096
#define N_COLS 4096
#define D_K    512

#define TILE_M 128
#define TILE_N 128
#define KC     16
#define NCHUNK (D_K / KC)          // 32

// smem geometry (floats): row stride 20 (pad 4 -> conflict-free frags,
// 16B-aligned cp.async destinations)
#define RS        20
#define ARR_F     (128 * RS)       // 2560 floats per operand array
#define STAGE_F   (4 * ARR_F)      // Ah, Al, Bh, Bl
#define SMEM_F    (2 * STAGE_F)
#define SMEM_BYTES (SMEM_F * 4)    // 81920

// ---------------- scratch (__device__ globals; no allocation allowed) -------
__device__ float g_xh[B_ROWS * D_K];
__device__ float g_xl[B_ROWS * D_K];
__device__ float g_wh[N_COLS * D_K];
__device__ float g_wl[N_COLS * D_K];
__device__ float g_xsq[B_ROWS];
__device__ float g_wsq[N_COLS];
__device__ unsigned long long g_best[B_ROWS];

// ---------------- PTX helpers ----------------------------------------------
__device__ __forceinline__ uint32_t smem_u32(const void* p) {
    uint32_t a;
    asm("{ .reg .u64 t; cvta.to.shared.u64 t, %1; cvt.u32.u64 %0, t; }"
        : "=r"(a) : "l"(p));
    return a;
}
#define CP16(sa, ga) \
    asm volatile("cp.async.cg.shared.global [%0], [%1], 16;" \
                 :: "r"(sa), "l"(ga) : "memory")
#define CP_COMMIT()  asm volatile("cp.async.commit_group;" ::: "memory")
#define CP_WAIT1()   asm volatile("cp.async.wait_group 1;" ::: "memory")
#define CP_WAIT0()   asm volatile("cp.async.wait_group 0;" ::: "memory")

__device__ __forceinline__ void mma1688(float* d, const uint32_t* a,
                                        const uint32_t* b) {
    asm volatile(
        "mma.sync.aligned.m16n8k8.row.col.f32.tf32.tf32.f32 "
        "{%0,%1,%2,%3}, {%4,%5,%6,%7}, {%8,%9}, {%0,%1,%2,%3};"
        : "+f"(d[0]), "+f"(d[1]), "+f"(d[2]), "+f"(d[3])
        : "r"(a[0]), "r"(a[1]), "r"(a[2]), "r"(a[3]), "r"(b[0]), "r"(b[1]));
}
__device__ __forceinline__ uint32_t tf32_rna(float v) {
    uint32_t r;
    asm("cvt.rna.tf32.f32 %0, %1;" : "=r"(r) : "f"(v));
    return r;
}

// ---------------------------------------------------------------------------
// Kernel 0: split fp32 -> (tf32 hi, tf32 lo), per-row sumsq, init g_best.
// One warp per row (x rows first, then w rows).
// ---------------------------------------------------------------------------
__global__ void prep_kernel(const float* __restrict__ x,
                            const float* __restrict__ w) {
    int warp = (blockIdx.x * blockDim.x + threadIdx.x) >> 5;
    int lane = threadIdx.x & 31;
    if (warp >= B_ROWS + N_COLS) return;
    bool isx = (warp < B_ROWS);
    int row = isx ? warp : warp - B_ROWS;
    const float* src = isx ? (x + (size_t)row * D_K) : (w + (size_t)row * D_K);
    float* dh = isx ? (g_xh + (size_t)row * D_K) : (g_wh + (size_t)row * D_K);
    float* dl = isx ? (g_xl + (size_t)row * D_K) : (g_wl + (size_t)row * D_K);

    float s = 0.f;
    #pragma unroll
    for (int k = lane * 4; k < D_K; k += 128) {
        float4 v = *reinterpret_cast<const float4*>(src + k);
        s += v.x * v.x + v.y * v.y + v.z * v.z + v.w * v.w;
        float4 h, l;
        h.x = __uint_as_float(tf32_rna(v.x));
        h.y = __uint_as_float(tf32_rna(v.y));
        h.z = __uint_as_float(tf32_rna(v.z));
        h.w = __uint_as_float(tf32_rna(v.w));
        l.x = __uint_as_float(tf32_rna(v.x - h.x));
        l.y = __uint_as_float(tf32_rna(v.y - h.y));
        l.z = __uint_as_float(tf32_rna(v.z - h.z));
        l.w = __uint_as_float(tf32_rna(v.w - h.w));
        *reinterpret_cast<float4*>(dh + k) = h;
        *reinterpret_cast<float4*>(dl + k) = l;
    }
    #pragma unroll
    for (int o = 16; o; o >>= 1) s += __shfl_xor_sync(0xffffffffu, s, o);
    if (lane == 0) {
        if (isx) { g_xsq[row] = s; g_best[row] = 0xFFFFFFFFFFFFFFFFull; }
        else     { g_wsq[row] = s; }
    }
}

// ---------------------------------------------------------------------------
// Kernel 1: tf32 split GEMM via mma.sync (tensor pipe) + fused argmin.
// CTA 128x128, 8 warps in 2(m) x 4(n); warp tile 64x32 = 4x4 m16n8 tiles.
// dot = Xh.Wh + Xh.Wl + Xl.Wh accumulated in fp32.
// ---------------------------------------------------------------------------
__global__ __launch_bounds__(256, 1)
void som_mma_kernel() {
    extern __shared__ float smem[];
    const uint32_t sb = smem_u32(smem);
    const int tid  = threadIdx.x;
    const int wid  = tid >> 5;
    const int lane = tid & 31;
    const int gid  = lane >> 2;      // group id 0..7
    const int tg   = lane & 3;       // thread-in-group 0..3
    const int wm   = wid & 1;        // warp m index (0..1)
    const int wn   = wid >> 1;       // warp n index (0..3)
    const int m0 = blockIdx.x * TILE_M;
    const int n0 = blockIdx.y * TILE_N;

    float acc[4][4][4];
    #pragma unroll
    for (int mi = 0; mi < 4; mi++)
        #pragma unroll
        for (int ni = 0; ni < 4; ni++)
            #pragma unroll
            for (int c = 0; c < 4; c++) acc[mi][ni][c] = 0.f;

    // chunk loader: 8 cp.async per thread (Ah, Al, Bh, Bl x 2 rows-segs)
    auto load_chunk = [&](int kc, int s) {
        const int kb = kc * KC;
        const uint32_t stage = sb + (uint32_t)(s * STAGE_F * 4);
        #pragma unroll
        for (int j = 0; j < 2; j++) {
            int idx = tid + j * 256;            // 0..511
            int row = idx >> 2, seg = idx & 3;  // 128 rows x 4 16B-segs
            uint32_t so = (uint32_t)((row * RS + seg * 4) * 4);
            size_t goA = (size_t)(m0 + row) * D_K + kb + seg * 4;
            size_t goB = (size_t)(n0 + row) * D_K + kb + seg * 4;
            CP16(stage + 0 * ARR_F * 4 + so, (const void*)(g_xh + goA));
            CP16(stage + 1 * ARR_F * 4 + so, (const void*)(g_xl + goA));
            CP16(stage + 2 * ARR_F * 4 + so, (const void*)(g_wh + goB));
            CP16(stage + 3 * ARR_F * 4 + so, (const void*)(g_wl + goB));
        }
        CP_COMMIT();
    };

    load_chunk(0, 0);

    for (int i = 0; i < NCHUNK; i++) {
        if (i + 1 < NCHUNK) { load_chunk(i + 1, (i + 1) & 1); CP_WAIT1(); }
        else                { CP_WAIT0(); }
        __syncthreads();

        const float* st  = smem + (i & 1) * STAGE_F;
        const uint32_t* sAh = (const uint32_t*)(st);
        const uint32_t* sAl = (const uint32_t*)(st + ARR_F);
        const uint32_t* sBh = (const uint32_t*)(st + 2 * ARR_F);
        const uint32_t* sBl = (const uint32_t*)(st + 3 * ARR_F);

        #pragma unroll
        for (int ks = 0; ks < 2; ks++) {
            const int ko = ks * 8 + tg;
            uint32_t ah[4][4], al[4][4], bh[4][2], bl[4][2];
            #pragma unroll
            for (int mi = 0; mi < 4; mi++) {
                int r = (wm * 64 + mi * 16 + gid) * RS + ko;
                ah[mi][0] = sAh[r];            ah[mi][2] = sAh[r + 4];
                ah[mi][1] = sAh[r + 8 * RS];   ah[mi][3] = sAh[r + 8 * RS + 4];
                al[mi][0] = sAl[r];            al[mi][2] = sAl[r + 4];
                al[mi][1] = sAl[r + 8 * RS];   al[mi][3] = sAl[r + 8 * RS + 4];
            }
            #pragma unroll
            for (int ni = 0; ni < 4; ni++) {
                int r = (wn * 32 + ni * 8 + gid) * RS + ko;
                bh[ni][0] = sBh[r]; bh[ni][1] = sBh[r + 4];
                bl[ni][0] = sBl[r]; bl[ni][1] = sBl[r + 4];
            }
            #pragma unroll
            for (int mi = 0; mi < 4; mi++)
                #pragma unroll
                for (int ni = 0; ni < 4; ni++) {
                    mma1688(acc[mi][ni], ah[mi], bh[ni]);
                    mma1688(acc[mi][ni], ah[mi], bl[ni]);
                    mma1688(acc[mi][ni], al[mi], bh[ni]);
                }
        }
        __syncthreads();
    }

    // ---- epilogue: combine + per-row argmin -------------------------------
    float ws[4][2];
    #pragma unroll
    for (int ni = 0; ni < 4; ni++) {
        int col = n0 + wn * 32 + ni * 8 + tg * 2;
        ws[ni][0] = g_wsq[col];
        ws[ni][1] = g_wsq[col + 1];
    }

    #pragma unroll
    for (int mi = 0; mi < 4; mi++) {
        #pragma unroll
        for (int h = 0; h < 2; h++) {
            const int row = m0 + wm * 64 + mi * 16 + gid + h * 8;
            const float xs = g_xsq[row];
            unsigned long long best = 0xFFFFFFFFFFFFFFFFull;
            #pragma unroll
            for (int ni = 0; ni < 4; ni++) {
                #pragma unroll
                for (int c = 0; c < 2; c++) {
                    const int col = n0 + wn * 32 + ni * 8 + tg * 2 + c;
                    const float dot = acc[mi][ni][h * 2 + c];
                    float t = __fsub_rn(xs, __fmul_rn(2.0f, dot));
                    float v = __fadd_rn(t, ws[ni][c]);
                    v = fmaxf(v, 0.0f);
                    unsigned long long u =
                        ((unsigned long long)__float_as_uint(v) << 32) |
                        (unsigned long long)(uint32_t)col;
                    best = (u < best) ? u : best;
                }
            }
            // reduce across the 4 lanes (tg) sharing this row
            unsigned long long o;
            o = __shfl_xor_sync(0xffffffffu, best, 1); best = (o < best) ? o : best;
            o = __shfl_xor_sync(0xffffffffu, best, 2); best = (o < best) ? o : best;
            if (tg == 0) atomicMin(&g_best[row], best);
        }
    }
}

// ---------------------------------------------------------------------------
// Kernel 2: unpack g_best -> outputs.
// Layout (float32): [B*2] bmu (y,x) then [B] quantization errors.
// ---------------------------------------------------------------------------
__global__ void out_kernel(float* __restrict__ out) {
    int r = blockIdx.x * blockDim.x + threadIdx.x;
    if (r >= B_ROWS) return;
    unsigned long long p = g_best[r];
    int col = (int)(p & 0xFFFFFFFFull);
    float v = __uint_as_float((uint32_t)(p >> 32));
    out[2 * r]     = (float)(col >> 6);   // y = idx / 64
    out[2 * r + 1] = (float)(col & 63);   // x = idx % 64
    out[2 * B_ROWS + r] = sqrtf(v);
}

extern "C" void kernel_launch(void* const* d_in, const int* in_sizes, int n_in,
                              void* d_out, int out_size) {
    const float* x = (const float*)d_in[0];   // inputs      (4096, 512)
    const float* w = (const float*)d_in[1];   // weights_map (64, 64, 512)
    float* out = (float*)d_out;

    static int smem_set = 0;
    if (!smem_set) {
        cudaFuncSetAttribute(som_mma_kernel,
                             cudaFuncAttributeMaxDynamicSharedMemorySize,
                             SMEM_BYTES);
        smem_set = 1;
    }

    {
        int warps = B_ROWS + N_COLS;
        int blocks = (warps * 32 + 255) / 256;
        prep_kernel<<<blocks, 256>>>(x, w);
    }
    {
        dim3 grid(B_ROWS / TILE_M, N_COLS / TILE_N);   // (32, 32)
        som_mma_kernel<<<grid, 256, SMEM_BYTES>>>();
    }
    {
        out_kernel<<<(B_ROWS + 255) / 256, 256>>>(out);
    }
}

// round 5
// speedup vs baseline: 3.6444x; 1.8534x over previous
#include <cuda_runtime.h>
#include <cuda_fp16.h>
#include <math.h>
#include <stdint.h>

#define B_ROWS 4096
#define N_COLS 4096
#define D_K    512

#define TILE_M 128
#define TILE_N 128
#define KC     16
#define NCHUNK (D_K / KC)          // 32

// smem geometry: rows of 16 halves padded to 24 halves (48 B) -> 16B-aligned
// cp.async segs AND conflict-free fragment LDS (stride 12 words).
#define RSH        24              // row stride in halves
#define ARR_B      (128 * RSH * 2) // 6144 bytes per operand array
#define STAGE_B    (4 * ARR_B)     // Ah, Al, Bh, Bl = 24576
#define SMEM_BYTES (2 * STAGE_B)   // 49152

// ---------------- scratch (__device__ globals; no allocation allowed) -------
__device__ __half g_xh[B_ROWS * D_K];
__device__ __half g_xl[B_ROWS * D_K];
__device__ __half g_wh[N_COLS * D_K];
__device__ __half g_wl[N_COLS * D_K];
__device__ float g_xsq[B_ROWS];
__device__ float g_wsq[N_COLS];
__device__ unsigned long long g_best[B_ROWS];

// ---------------- PTX helpers ----------------------------------------------
__device__ __forceinline__ uint32_t smem_u32(const void* p) {
    uint32_t a;
    asm("{ .reg .u64 t; cvta.to.shared.u64 t, %1; cvt.u32.u64 %0, t; }"
        : "=r"(a) : "l"(p));
    return a;
}
#define CP16(sa, ga) \
    asm volatile("cp.async.cg.shared.global [%0], [%1], 16;" \
                 :: "r"(sa), "l"(ga) : "memory")
#define CP_COMMIT()  asm volatile("cp.async.commit_group;" ::: "memory")
#define CP_WAIT1()   asm volatile("cp.async.wait_group 1;" ::: "memory")
#define CP_WAIT0()   asm volatile("cp.async.wait_group 0;" ::: "memory")

__device__ __forceinline__ void mma16816(float* d, const uint32_t* a,
                                         const uint32_t* b) {
    asm volatile(
        "mma.sync.aligned.m16n8k16.row.col.f32.f16.f16.f32 "
        "{%0,%1,%2,%3}, {%4,%5,%6,%7}, {%8,%9}, {%0,%1,%2,%3};"
        : "+f"(d[0]), "+f"(d[1]), "+f"(d[2]), "+f"(d[3])
        : "r"(a[0]), "r"(a[1]), "r"(a[2]), "r"(a[3]), "r"(b[0]), "r"(b[1]));
}

// ---------------------------------------------------------------------------
// Kernel 0: split fp32 -> (fp16 hi, fp16 lo), per-row sumsq, init g_best.
// One warp per row (x rows first, then w rows).
// ---------------------------------------------------------------------------
__global__ void prep_kernel(const float* __restrict__ x,
                            const float* __restrict__ w) {
    int warp = (blockIdx.x * blockDim.x + threadIdx.x) >> 5;
    int lane = threadIdx.x & 31;
    if (warp >= B_ROWS + N_COLS) return;
    bool isx = (warp < B_ROWS);
    int row = isx ? warp : warp - B_ROWS;
    const float* src = isx ? (x + (size_t)row * D_K) : (w + (size_t)row * D_K);
    __half* dh = isx ? (g_xh + (size_t)row * D_K) : (g_wh + (size_t)row * D_K);
    __half* dl = isx ? (g_xl + (size_t)row * D_K) : (g_wl + (size_t)row * D_K);

    float s = 0.f;
    #pragma unroll
    for (int k = lane * 4; k < D_K; k += 128) {
        float4 v = *reinterpret_cast<const float4*>(src + k);
        s += v.x * v.x + v.y * v.y + v.z * v.z + v.w * v.w;
        __half h0 = __float2half_rn(v.x), h1 = __float2half_rn(v.y);
        __half h2 = __float2half_rn(v.z), h3 = __float2half_rn(v.w);
        __half l0 = __float2half_rn(v.x - __half2float(h0));
        __half l1 = __float2half_rn(v.y - __half2float(h1));
        __half l2 = __float2half_rn(v.z - __half2float(h2));
        __half l3 = __float2half_rn(v.w - __half2float(h3));
        __half2 hp[2] = { __halves2half2(h0, h1), __halves2half2(h2, h3) };
        __half2 lp[2] = { __halves2half2(l0, l1), __halves2half2(l2, l3) };
        *reinterpret_cast<uint2*>(dh + k) = *reinterpret_cast<uint2*>(hp);
        *reinterpret_cast<uint2*>(dl + k) = *reinterpret_cast<uint2*>(lp);
    }
    #pragma unroll
    for (int o = 16; o; o >>= 1) s += __shfl_xor_sync(0xffffffffu, s, o);
    if (lane == 0) {
        if (isx) { g_xsq[row] = s; g_best[row] = 0xFFFFFFFFFFFFFFFFull; }
        else     { g_wsq[row] = s; }
    }
}

// ---------------------------------------------------------------------------
// Kernel 1: fp16 split GEMM via mma.sync m16n8k16 + fused argmin.
// CTA 128x128, 8 warps in 2(m) x 4(n); warp tile 64x32 = 4x4 m16n8 tiles.
// dot = Xh.Wh + Xh.Wl + Xl.Wh accumulated in fp32 (each product exact).
// ---------------------------------------------------------------------------
__global__ __launch_bounds__(256)
void som_mma_kernel() {
    extern __shared__ char smem[];
    const uint32_t sb = smem_u32(smem);
    const int tid  = threadIdx.x;
    const int wid  = tid >> 5;
    const int lane = tid & 31;
    const int gid  = lane >> 2;      // 0..7
    const int tg   = lane & 3;       // 0..3
    const int wm   = wid & 1;        // warp m index (0..1)
    const int wn   = wid >> 1;       // warp n index (0..3)
    const int m0 = blockIdx.x * TILE_M;
    const int n0 = blockIdx.y * TILE_N;

    float acc[4][4][4];
    #pragma unroll
    for (int mi = 0; mi < 4; mi++)
        #pragma unroll
        for (int ni = 0; ni < 4; ni++)
            #pragma unroll
            for (int c = 0; c < 4; c++) acc[mi][ni][c] = 0.f;

    // chunk loader: 4 cp.async per thread (one 16B seg per operand array)
    // array layout: 128 rows x 2 segs; slot = tid (256 slots).
    auto load_chunk = [&](int kc, int s) {
        const int kb = kc * KC;
        const uint32_t stage = sb + (uint32_t)(s * STAGE_B);
        const int row = tid >> 1, seg = tid & 1;
        const uint32_t so = (uint32_t)(row * (RSH * 2) + seg * 16);
        const size_t goA = (size_t)(m0 + row) * D_K + kb + seg * 8;
        const size_t goB = (size_t)(n0 + row) * D_K + kb + seg * 8;
        CP16(stage + 0 * ARR_B + so, (const void*)(g_xh + goA));
        CP16(stage + 1 * ARR_B + so, (const void*)(g_xl + goA));
        CP16(stage + 2 * ARR_B + so, (const void*)(g_wh + goB));
        CP16(stage + 3 * ARR_B + so, (const void*)(g_wl + goB));
        CP_COMMIT();
    };

    load_chunk(0, 0);

    for (int i = 0; i < NCHUNK; i++) {
        if (i + 1 < NCHUNK) { load_chunk(i + 1, (i + 1) & 1); CP_WAIT1(); }
        else                { CP_WAIT0(); }
        __syncthreads();

        const char* st = smem + (i & 1) * STAGE_B;
        const uint32_t* sAh = (const uint32_t*)(st);
        const uint32_t* sAl = (const uint32_t*)(st + ARR_B);
        const uint32_t* sBh = (const uint32_t*)(st + 2 * ARR_B);
        const uint32_t* sBl = (const uint32_t*)(st + 3 * ARR_B);
        const int RW = RSH / 2;      // 12 words per row

        // B fragments for the whole chunk (4 n-tiles x 2 regs x {h,l})
        uint32_t bh[4][2], bl[4][2];
        #pragma unroll
        for (int ni = 0; ni < 4; ni++) {
            int r = (wn * 32 + ni * 8 + gid) * RW + tg;
            bh[ni][0] = sBh[r]; bh[ni][1] = sBh[r + 4];
            bl[ni][0] = sBl[r]; bl[ni][1] = sBl[r + 4];
        }
        #pragma unroll
        for (int mi = 0; mi < 4; mi++) {
            int r = (wm * 64 + mi * 16 + gid) * RW + tg;
            uint32_t ah[4], al[4];
            ah[0] = sAh[r];           ah[2] = sAh[r + 4];
            ah[1] = sAh[r + 8 * RW];  ah[3] = sAh[r + 8 * RW + 4];
            al[0] = sAl[r];           al[2] = sAl[r + 4];
            al[1] = sAl[r + 8 * RW];  al[3] = sAl[r + 8 * RW + 4];
            #pragma unroll
            for (int ni = 0; ni < 4; ni++) {
                mma16816(acc[mi][ni], ah, bh[ni]);
                mma16816(acc[mi][ni], ah, bl[ni]);
                mma16816(acc[mi][ni], al, bh[ni]);
            }
        }
        __syncthreads();
    }

    // ---- epilogue: combine + per-row argmin -------------------------------
    float ws[4][2];
    #pragma unroll
    for (int ni = 0; ni < 4; ni++) {
        int col = n0 + wn * 32 + ni * 8 + tg * 2;
        ws[ni][0] = g_wsq[col];
        ws[ni][1] = g_wsq[col + 1];
    }

    #pragma unroll
    for (int mi = 0; mi < 4; mi++) {
        #pragma unroll
        for (int h = 0; h < 2; h++) {
            const int row = m0 + wm * 64 + mi * 16 + gid + h * 8;
            const float xs = g_xsq[row];
            unsigned long long best = 0xFFFFFFFFFFFFFFFFull;
            #pragma unroll
            for (int ni = 0; ni < 4; ni++) {
                #pragma unroll
                for (int c = 0; c < 2; c++) {
                    const int col = n0 + wn * 32 + ni * 8 + tg * 2 + c;
                    const float dot = acc[mi][ni][h * 2 + c];
                    float t = __fsub_rn(xs, __fmul_rn(2.0f, dot));
                    float v = __fadd_rn(t, ws[ni][c]);
                    v = fmaxf(v, 0.0f);
                    unsigned long long u =
                        ((unsigned long long)__float_as_uint(v) << 32) |
                        (unsigned long long)(uint32_t)col;
                    best = (u < best) ? u : best;
                }
            }
            unsigned long long o;
            o = __shfl_xor_sync(0xffffffffu, best, 1); best = (o < best) ? o : best;
            o = __shfl_xor_sync(0xffffffffu, best, 2); best = (o < best) ? o : best;
            if (tg == 0) atomicMin(&g_best[row], best);
        }
    }
}

// ---------------------------------------------------------------------------
// Kernel 2: unpack g_best -> outputs.
// Layout (float32): [B*2] bmu (y,x) then [B] quantization errors.
// ---------------------------------------------------------------------------
__global__ void out_kernel(float* __restrict__ out) {
    int r = blockIdx.x * blockDim.x + threadIdx.x;
    if (r >= B_ROWS) return;
    unsigned long long p = g_best[r];
    int col = (int)(p & 0xFFFFFFFFull);
    float v = __uint_as_float((uint32_t)(p >> 32));
    out[2 * r]     = (float)(col >> 6);   // y = idx / 64
    out[2 * r + 1] = (float)(col & 63);   // x = idx % 64
    out[2 * B_ROWS + r] = sqrtf(v);
}

extern "C" void kernel_launch(void* const* d_in, const int* in_sizes, int n_in,
                              void* d_out, int out_size) {
    const float* x = (const float*)d_in[0];   // inputs      (4096, 512)
    const float* w = (const float*)d_in[1];   // weights_map (64, 64, 512)
    float* out = (float*)d_out;

    static int smem_set = 0;
    if (!smem_set) {
        cudaFuncSetAttribute(som_mma_kernel,
                             cudaFuncAttributeMaxDynamicSharedMemorySize,
                             SMEM_BYTES);
        smem_set = 1;
    }

    {
        int warps = B_ROWS + N_COLS;
        int blocks = (warps * 32 + 255) / 256;
        prep_kernel<<<blocks, 256>>>(x, w);
    }
    {
        dim3 grid(B_ROWS / TILE_M, N_COLS / TILE_N);   // (32, 32)
        som_mma_kernel<<<grid, 256, SMEM_BYTES>>>();
    }
    {
        out_kernel<<<(B_ROWS + 255) / 256, 256>>>(out);
    }
}

// round 6
// speedup vs baseline: 5.5413x; 1.5205x over previous
#include <cuda_runtime.h>
#include <cuda_fp16.h>
#include <math.h>
#include <stdint.h>

#define B_ROWS 4096
#define N_COLS 4096
#define D_K    512

#define TILE_M 128
#define TILE_N 128
#define KC     16
#define NCHUNK (D_K / KC)          // 32
#define NSTAGE 4

// smem geometry: rows of 16 halves padded to 24 halves (48 B) -> 16B-aligned
// cp.async segs AND conflict-free fragment LDS (stride 12 words).
#define RSH        24
#define ARR_B      (128 * RSH * 2) // 6144 bytes per operand array
#define STAGE_B    (2 * ARR_B)     // Ah, Bh = 12288
#define SMEM_BYTES (NSTAGE * STAGE_B) // 49152

#define CAP 64                     // candidate list capacity per row

// ---------------- scratch (__device__ globals; no allocation allowed) -------
__device__ __half g_xh[B_ROWS * D_K];
__device__ __half g_wh[N_COLS * D_K];
__device__ float g_xsq[B_ROWS];
__device__ float g_wsq[N_COLS];
__device__ float g_xl2[B_ROWS];        // ||xl||^2 per row
__device__ float g_xh2[B_ROWS];        // ||xh||^2 per row
__device__ unsigned int g_whmax2;      // max_c ||wh_c||^2 (float bits)
__device__ unsigned int g_wlmax2;      // max_c ||wl_c||^2 (float bits)
__device__ unsigned long long g_best[B_ROWS];
__device__ float g_approx[(size_t)B_ROWS * N_COLS];   // 67 MB approx sq_dist

// ---------------- PTX helpers ----------------------------------------------
__device__ __forceinline__ uint32_t smem_u32(const void* p) {
    uint32_t a;
    asm("{ .reg .u64 t; cvta.to.shared.u64 t, %1; cvt.u32.u64 %0, t; }"
        : "=r"(a) : "l"(p));
    return a;
}
#define CP16(sa, ga) \
    asm volatile("cp.async.cg.shared.global [%0], [%1], 16;" \
                 :: "r"(sa), "l"(ga) : "memory")
#define CP_COMMIT()  asm volatile("cp.async.commit_group;" ::: "memory")
#define CP_WAIT3()   asm volatile("cp.async.wait_group 3;" ::: "memory")
#define CP_WAIT0()   asm volatile("cp.async.wait_group 0;" ::: "memory")

__device__ __forceinline__ void mma16816(float* d, const uint32_t* a,
                                         const uint32_t* b) {
    asm volatile(
        "mma.sync.aligned.m16n8k16.row.col.f32.f16.f16.f32 "
        "{%0,%1,%2,%3}, {%4,%5,%6,%7}, {%8,%9}, {%0,%1,%2,%3};"
        : "+f"(d[0]), "+f"(d[1]), "+f"(d[2]), "+f"(d[3])
        : "r"(a[0]), "r"(a[1]), "r"(a[2]), "r"(a[3]), "r"(b[0]), "r"(b[1]));
}

// ---------------------------------------------------------------------------
// Kernel -1: zero the global maxima (must precede prep's atomicMax).
// ---------------------------------------------------------------------------
__global__ void init_kernel() {
    g_whmax2 = 0u;
    g_wlmax2 = 0u;
}

// ---------------------------------------------------------------------------
// Kernel 0: fp16 hi plane + norms. One warp per row (x rows, then w rows).
// ---------------------------------------------------------------------------
__global__ void prep_kernel(const float* __restrict__ x,
                            const float* __restrict__ w) {
    int warp = (blockIdx.x * blockDim.x + threadIdx.x) >> 5;
    int lane = threadIdx.x & 31;
    if (warp >= B_ROWS + N_COLS) return;
    bool isx = (warp < B_ROWS);
    int row = isx ? warp : warp - B_ROWS;
    const float* src = isx ? (x + (size_t)row * D_K) : (w + (size_t)row * D_K);
    __half* dh = isx ? (g_xh + (size_t)row * D_K) : (g_wh + (size_t)row * D_K);

    float s = 0.f, sl = 0.f, sh = 0.f;
    #pragma unroll
    for (int k = lane * 4; k < D_K; k += 128) {
        float4 v = *reinterpret_cast<const float4*>(src + k);
        s += v.x * v.x + v.y * v.y + v.z * v.z + v.w * v.w;
        __half h0 = __float2half_rn(v.x), h1 = __float2half_rn(v.y);
        __half h2 = __float2half_rn(v.z), h3 = __float2half_rn(v.w);
        float f0 = __half2float(h0), f1 = __half2float(h1);
        float f2 = __half2float(h2), f3 = __half2float(h3);
        sh += f0 * f0 + f1 * f1 + f2 * f2 + f3 * f3;
        float e0 = v.x - f0, e1 = v.y - f1, e2 = v.z - f2, e3 = v.w - f3;
        sl += e0 * e0 + e1 * e1 + e2 * e2 + e3 * e3;
        __half2 hp[2] = { __halves2half2(h0, h1), __halves2half2(h2, h3) };
        *reinterpret_cast<uint2*>(dh + k) = *reinterpret_cast<uint2*>(hp);
    }
    #pragma unroll
    for (int o = 16; o; o >>= 1) {
        s  += __shfl_xor_sync(0xffffffffu, s, o);
        sl += __shfl_xor_sync(0xffffffffu, sl, o);
        sh += __shfl_xor_sync(0xffffffffu, sh, o);
    }
    if (lane == 0) {
        if (isx) {
            g_xsq[row] = s; g_xl2[row] = sl; g_xh2[row] = sh;
            g_best[row] = 0xFFFFFFFFFFFFFFFFull;
        } else {
            g_wsq[row] = s;
            atomicMax(&g_whmax2, __float_as_uint(sh));  // non-neg floats: bit order ok
            atomicMax(&g_wlmax2, __float_as_uint(sl));
        }
    }
}

// ---------------------------------------------------------------------------
// Kernel 1: fp16 hh-only GEMM (approx) + store approx matrix + per-row min.
// CTA 128x128, 8 warps in 2(m) x 4(n); 4-stage cp.async pipeline.
// ---------------------------------------------------------------------------
__global__ __launch_bounds__(256)
void som_mma_kernel() {
    extern __shared__ char smem[];
    const uint32_t sb = smem_u32(smem);
    const int tid  = threadIdx.x;
    const int wid  = tid >> 5;
    const int lane = tid & 31;
    const int gid  = lane >> 2;
    const int tg   = lane & 3;
    const int wm   = wid & 1;
    const int wn   = wid >> 1;
    const int m0 = blockIdx.x * TILE_M;
    const int n0 = blockIdx.y * TILE_N;

    float acc[4][4][4];
    #pragma unroll
    for (int mi = 0; mi < 4; mi++)
        #pragma unroll
        for (int ni = 0; ni < 4; ni++)
            #pragma unroll
            for (int c = 0; c < 4; c++) acc[mi][ni][c] = 0.f;

    const int lrow = tid >> 1, lseg = tid & 1;
    const uint32_t lso = (uint32_t)(lrow * (RSH * 2) + lseg * 16);

    auto load_chunk = [&](int kc) {
        const int kb = kc * KC;
        const uint32_t stage = sb + (uint32_t)((kc % NSTAGE) * STAGE_B);
        CP16(stage + 0 * ARR_B + lso,
             (const void*)(g_xh + (size_t)(m0 + lrow) * D_K + kb + lseg * 8));
        CP16(stage + 1 * ARR_B + lso,
             (const void*)(g_wh + (size_t)(n0 + lrow) * D_K + kb + lseg * 8));
        CP_COMMIT();
    };

    load_chunk(0); load_chunk(1); load_chunk(2);

    for (int i = 0; i < NCHUNK; i++) {
        if (i + 3 < NCHUNK) { load_chunk(i + 3); CP_WAIT3(); }
        else                { CP_WAIT0(); }
        __syncthreads();

        const char* st = smem + (i % NSTAGE) * STAGE_B;
        const uint32_t* sAh = (const uint32_t*)(st);
        const uint32_t* sBh = (const uint32_t*)(st + ARR_B);
        const int RW = RSH / 2;  // 12

        uint32_t bh[4][2];
        #pragma unroll
        for (int ni = 0; ni < 4; ni++) {
            int r = (wn * 32 + ni * 8 + gid) * RW + tg;
            bh[ni][0] = sBh[r]; bh[ni][1] = sBh[r + 4];
        }
        #pragma unroll
        for (int mi = 0; mi < 4; mi++) {
            int r = (wm * 64 + mi * 16 + gid) * RW + tg;
            uint32_t ah[4];
            ah[0] = sAh[r];           ah[2] = sAh[r + 4];
            ah[1] = sAh[r + 8 * RW];  ah[3] = sAh[r + 8 * RW + 4];
            #pragma unroll
            for (int ni = 0; ni < 4; ni++)
                mma16816(acc[mi][ni], ah, bh[ni]);
        }
        __syncthreads();
    }

    // ---- epilogue: combine, store approx matrix, per-row approx argmin ----
    float ws[4][2];
    #pragma unroll
    for (int ni = 0; ni < 4; ni++) {
        int col = n0 + wn * 32 + ni * 8 + tg * 2;
        ws[ni][0] = g_wsq[col];
        ws[ni][1] = g_wsq[col + 1];
    }

    #pragma unroll
    for (int mi = 0; mi < 4; mi++) {
        #pragma unroll
        for (int h = 0; h < 2; h++) {
            const int row = m0 + wm * 64 + mi * 16 + gid + h * 8;
            const float xs = g_xsq[row];
            unsigned long long best = 0xFFFFFFFFFFFFFFFFull;
            #pragma unroll
            for (int ni = 0; ni < 4; ni++) {
                const int col = n0 + wn * 32 + ni * 8 + tg * 2;
                float2 vv;
                #pragma unroll
                for (int c = 0; c < 2; c++) {
                    const float dot = acc[mi][ni][h * 2 + c];
                    float t = __fsub_rn(xs, __fmul_rn(2.0f, dot));
                    float v = fmaxf(__fadd_rn(t, ws[ni][c]), 0.0f);
                    (&vv.x)[c] = v;
                    unsigned long long u =
                        ((unsigned long long)__float_as_uint(v) << 32) |
                        (unsigned long long)(uint32_t)(col + c);
                    best = (u < best) ? u : best;
                }
                *reinterpret_cast<float2*>(
                    g_approx + (size_t)row * N_COLS + col) = vv;
            }
            unsigned long long o;
            o = __shfl_xor_sync(0xffffffffu, best, 1); best = (o < best) ? o : best;
            o = __shfl_xor_sync(0xffffffffu, best, 2); best = (o < best) ? o : best;
            if (tg == 0) atomicMin(&g_best[row], best);
        }
    }
}

// ---------------------------------------------------------------------------
// Kernel 2: per-row screen + exact rescreen + output.
// One block (256 threads) per row.
// ---------------------------------------------------------------------------
__global__ __launch_bounds__(256)
void screen_kernel(const float* __restrict__ x, const float* __restrict__ w,
                   float* __restrict__ out) {
    const int r = blockIdx.x;
    const int tid = threadIdx.x;
    const int wid = tid >> 5;
    const int lane = tid & 31;

    __shared__ float xrow[D_K];
    __shared__ int cand[CAP];
    __shared__ int ncand;
    __shared__ float s_thr;
    __shared__ unsigned long long wbest[8];

    // load exact x row
    #pragma unroll
    for (int k = tid; k < D_K; k += 256) xrow[k] = x[(size_t)r * D_K + k];

    if (tid == 0) {
        ncand = 0;
        float minv = __uint_as_float((uint32_t)(g_best[r] >> 32));
        float whm = sqrtf(__uint_as_float(g_whmax2));
        float wlm = sqrtf(__uint_as_float(g_wlmax2));
        float xln = sqrtf(g_xl2[r]);
        float xhn = sqrtf(g_xh2[r]);
        // |v_exact - v_approx| <= 2*(xl.wh + xh.wl + xl.wl) bounds, 1.5x safety
        float epsPair = 3.0f * (xln * whm + xhn * wlm + xln * wlm) + 1e-4f;
        s_thr = minv + 2.0f * epsPair;
    }
    if (wid < 8 && lane == 0) wbest[wid] = 0xFFFFFFFFFFFFFFFFull;
    __syncthreads();

    const float thr = s_thr;
    const float* arow = g_approx + (size_t)r * N_COLS;
    #pragma unroll
    for (int j = 0; j < N_COLS / 256; j++) {
        int c = tid + j * 256;
        if (arow[c] <= thr) {
            int pos = atomicAdd(&ncand, 1);
            if (pos < CAP) cand[pos] = c;
        }
    }
    __syncthreads();

    const int nc = ncand;
    const float xs = g_xsq[r];
    unsigned long long best = 0xFFFFFFFFFFFFFFFFull;

    auto eval_col = [&](int col) {
        const float* wr = w + (size_t)col * D_K;
        float d = 0.f;
        #pragma unroll
        for (int k = 0; k < 16; k++) d += xrow[lane * 16 + k] * wr[lane * 16 + k];
        #pragma unroll
        for (int o = 16; o; o >>= 1) d += __shfl_xor_sync(0xffffffffu, d, o);
        float t = __fsub_rn(xs, __fmul_rn(2.0f, d));
        float v = fmaxf(__fadd_rn(t, g_wsq[col]), 0.0f);
        unsigned long long u = ((unsigned long long)__float_as_uint(v) << 32) |
                               (unsigned long long)(uint32_t)col;
        best = (u < best) ? u : best;
    };

    if (nc <= CAP) {
        for (int i = wid; i < nc; i += 8) eval_col(cand[i]);
    } else {
        for (int c = wid; c < N_COLS; c += 8) eval_col(c);   // rare fallback
    }
    if (lane == 0) wbest[wid] = best;
    __syncthreads();

    if (tid == 0) {
        unsigned long long b = wbest[0];
        #pragma unroll
        for (int i = 1; i < 8; i++) b = (wbest[i] < b) ? wbest[i] : b;
        int col = (int)(b & 0xFFFFFFFFull);
        float v = __uint_as_float((uint32_t)(b >> 32));
        out[2 * r]     = (float)(col >> 6);   // y = idx / 64
        out[2 * r + 1] = (float)(col & 63);   // x = idx % 64
        out[2 * B_ROWS + r] = sqrtf(v);
    }
}

extern "C" void kernel_launch(void* const* d_in, const int* in_sizes, int n_in,
                              void* d_out, int out_size) {
    const float* x = (const float*)d_in[0];   // inputs      (4096, 512)
    const float* w = (const float*)d_in[1];   // weights_map (64, 64, 512)
    float* out = (float*)d_out;

    static int smem_set = 0;
    if (!smem_set) {
        cudaFuncSetAttribute(som_mma_kernel,
                             cudaFuncAttributeMaxDynamicSharedMemorySize,
                             SMEM_BYTES);
        smem_set = 1;
    }

    init_kernel<<<1, 1>>>();
    {
        int warps = B_ROWS + N_COLS;
        int blocks = (warps * 32 + 255) / 256;
        prep_kernel<<<blocks, 256>>>(x, w);
    }
    {
        dim3 grid(B_ROWS / TILE_M, N_COLS / TILE_N);   // (32, 32)
        som_mma_kernel<<<grid, 256, SMEM_BYTES>>>();
    }
    screen_kernel<<<B_ROWS, 256>>>(x, w, out);
}